// round 1
// baseline (speedup 1.0000x reference)
#include <cuda_runtime.h>
#include <math.h>

#define TOK   4096          // B*S
#define SEQ   2048
#define EMB   1024
#define NHEAD 16
#define HDIM  64
#define FFD   4096

// -------- scratch (static device globals; no allocation in kernel_launch) ----
__device__ float g_h  [TOK * EMB];   // LN1 output
__device__ float g_q  [TOK * EMB];
__device__ float g_k  [TOK * EMB];
__device__ float g_v  [TOK * EMB];
__device__ float g_at [TOK * EMB];   // attention output (merged heads)
__device__ float g_x1 [TOK * EMB];   // residual 1 output
__device__ float g_h2 [TOK * EMB];   // LN2 output
__device__ float g_ff [TOK * FFD];   // FFN hidden

// ------------------------------- LayerNorm -----------------------------------
__global__ void ln_kernel(const float* __restrict__ x, const float* __restrict__ g,
                          const float* __restrict__ b, float* __restrict__ out) {
    int t = blockIdx.x;
    int tid = threadIdx.x;
    const float* row = x + (size_t)t * EMB;
    float vals[4];
    float sum = 0.f, sq = 0.f;
#pragma unroll
    for (int it = 0; it < 4; it++) {
        float v = row[tid + it * 256];
        vals[it] = v; sum += v; sq += v * v;
    }
    __shared__ float s1[256], s2[256];
    s1[tid] = sum; s2[tid] = sq;
    __syncthreads();
    for (int st = 128; st > 0; st >>= 1) {
        if (tid < st) { s1[tid] += s1[tid + st]; s2[tid] += s2[tid + st]; }
        __syncthreads();
    }
    float mu   = s1[0] * (1.f / EMB);
    float var  = s2[0] * (1.f / EMB) - mu * mu;
    float rstd = rsqrtf(var + 1e-5f);
#pragma unroll
    for (int it = 0; it < 4; it++) {
        int i = tid + it * 256;
        out[(size_t)t * EMB + i] = (vals[it] - mu) * rstd * g[i] + b[i];
    }
}

// ------------------------------- SGEMM ---------------------------------------
// C[M,N] = act( A[M,K] @ B[K,N] + bias[N] + (res ? res[M,N] : 0) )
// 64x64 tile, BK=16, 256 threads, 4x4 per thread. ACT: 0=none, 1=exact GELU.
template <int ACT>
__global__ void sgemm_kernel(const float* __restrict__ A, const float* __restrict__ B,
                             const float* __restrict__ bias, const float* __restrict__ res,
                             float* __restrict__ C, int M, int N, int K) {
    __shared__ float As[16][64];
    __shared__ float Bs[16][64];

    int tid  = threadIdx.x;
    int trow = tid >> 4;          // 0..15
    int tcol = tid & 15;          // 0..15
    int m0 = blockIdx.y * 64;
    int n0 = blockIdx.x * 64;

    // load mapping
    int a_m  = tid >> 2;          // 0..63
    int a_k4 = tid & 3;           // 0..3 (float4 within BK=16)
    int b_k  = tid >> 4;          // 0..15
    int b_n4 = tid & 15;          // 0..15

    float acc[4][4] = {};

    for (int k0 = 0; k0 < K; k0 += 16) {
        float4 av = *(const float4*)(A + (size_t)(m0 + a_m) * K + k0 + a_k4 * 4);
        As[a_k4 * 4 + 0][a_m] = av.x;
        As[a_k4 * 4 + 1][a_m] = av.y;
        As[a_k4 * 4 + 2][a_m] = av.z;
        As[a_k4 * 4 + 3][a_m] = av.w;
        *(float4*)&Bs[b_k][b_n4 * 4] =
            *(const float4*)(B + (size_t)(k0 + b_k) * N + n0 + b_n4 * 4);
        __syncthreads();
#pragma unroll
        for (int kk = 0; kk < 16; kk++) {
            float4 a4 = *(const float4*)&As[kk][trow * 4];
            float4 b4 = *(const float4*)&Bs[kk][tcol * 4];
            float a[4] = {a4.x, a4.y, a4.z, a4.w};
            float b[4] = {b4.x, b4.y, b4.z, b4.w};
#pragma unroll
            for (int i = 0; i < 4; i++)
#pragma unroll
                for (int j = 0; j < 4; j++)
                    acc[i][j] = fmaf(a[i], b[j], acc[i][j]);
        }
        __syncthreads();
    }

#pragma unroll
    for (int i = 0; i < 4; i++) {
        int m = m0 + trow * 4 + i;
#pragma unroll
        for (int j = 0; j < 4; j++) {
            int n = n0 + tcol * 4 + j;
            float v = acc[i][j] + bias[n];
            if (res) v += res[(size_t)m * N + n];
            if (ACT == 1) v = 0.5f * v * (1.f + erff(v * 0.70710678118654752f));
            C[(size_t)m * N + n] = v;
        }
    }
}

// ---------------------------- Flash attention --------------------------------
// grid: (S/64, B*NHEAD). Block 256 threads handles one 64-row Q tile of one head.
// Dynamic smem: Qs,Ks,Vs,Ss each 64x68 floats, + 3x64 stats.
#define AST 68
__global__ void attn_kernel(const float* __restrict__ Q, const float* __restrict__ K,
                            const float* __restrict__ V, float* __restrict__ O) {
    extern __shared__ float smem[];
    float* Qs = smem;                 // 64*68
    float* Ks = Qs + 64 * AST;
    float* Vs = Ks + 64 * AST;
    float* Ss = Vs + 64 * AST;
    float* m_s  = Ss + 64 * AST;      // 64
    float* l_s  = m_s + 64;           // 64
    float* resc = l_s + 64;           // 64

    int qt = blockIdx.x;
    int bh = blockIdx.y;
    int bb = bh / NHEAD;
    int hh = bh % NHEAD;
    int tid  = threadIdx.x;
    int trow = tid >> 4, tcol = tid & 15;

    size_t base = (size_t)bb * SEQ * EMB + (size_t)hh * HDIM;

    // load Q tile
#pragma unroll
    for (int it = 0; it < 4; it++) {
        int r  = (tid >> 4) + it * 16;
        int d4 = tid & 15;
        *(float4*)&Qs[r * AST + d4 * 4] =
            *(const float4*)(Q + base + (size_t)(qt * 64 + r) * EMB + d4 * 4);
    }
    if (tid < 64) { m_s[tid] = -1e30f; l_s[tid] = 0.f; }
    float o[4][4] = {};
    __syncthreads();

    const float scale = 0.125f;   // 1/sqrt(64)

    for (int kt = 0; kt <= qt; kt++) {
        // load K, V tiles
#pragma unroll
        for (int it = 0; it < 4; it++) {
            int r  = (tid >> 4) + it * 16;
            int d4 = tid & 15;
            size_t goff = base + (size_t)(kt * 64 + r) * EMB + d4 * 4;
            *(float4*)&Ks[r * AST + d4 * 4] = *(const float4*)(K + goff);
            *(float4*)&Vs[r * AST + d4 * 4] = *(const float4*)(V + goff);
        }
        __syncthreads();

        // S = Q K^T (4x4 per thread)
        float s[4][4] = {};
#pragma unroll
        for (int d4 = 0; d4 < 16; d4++) {
            float4 qv[4], kv[4];
#pragma unroll
            for (int i = 0; i < 4; i++)
                qv[i] = *(const float4*)&Qs[(trow * 4 + i) * AST + d4 * 4];
#pragma unroll
            for (int j = 0; j < 4; j++)
                kv[j] = *(const float4*)&Ks[(tcol * 4 + j) * AST + d4 * 4];
#pragma unroll
            for (int i = 0; i < 4; i++)
#pragma unroll
                for (int j = 0; j < 4; j++) {
                    s[i][j] = fmaf(qv[i].x, kv[j].x, s[i][j]);
                    s[i][j] = fmaf(qv[i].y, kv[j].y, s[i][j]);
                    s[i][j] = fmaf(qv[i].z, kv[j].z, s[i][j]);
                    s[i][j] = fmaf(qv[i].w, kv[j].w, s[i][j]);
                }
        }
        bool diag = (kt == qt);
#pragma unroll
        for (int i = 0; i < 4; i++) {
            int qr = trow * 4 + i;
#pragma unroll
            for (int j = 0; j < 4; j++) {
                int kr = tcol * 4 + j;
                float v = s[i][j] * scale;
                if (diag && kr > qr) v = -1e30f;
                Ss[qr * AST + kr] = v;
            }
        }
        __syncthreads();

        // online softmax per row (threads 0..63)
        if (tid < 64) {
            int r = tid;
            float mold = m_s[r];
            float rowmax = -1e30f;
#pragma unroll 8
            for (int c = 0; c < 64; c++) rowmax = fmaxf(rowmax, Ss[r * AST + c]);
            float mnew = fmaxf(mold, rowmax);
            float rs = __expf(mold - mnew);
            float sum = 0.f;
#pragma unroll 8
            for (int c = 0; c < 64; c++) {
                float p = __expf(Ss[r * AST + c] - mnew);
                Ss[r * AST + c] = p;
                sum += p;
            }
            l_s[r]  = l_s[r] * rs + sum;
            m_s[r]  = mnew;
            resc[r] = rs;
        }
        __syncthreads();

        // rescale accumulators, O += P @ V
#pragma unroll
        for (int i = 0; i < 4; i++) {
            float rs = resc[trow * 4 + i];
#pragma unroll
            for (int j = 0; j < 4; j++) o[i][j] *= rs;
        }
#pragma unroll 4
        for (int kr = 0; kr < 64; kr++) {
            float4 vv = *(const float4*)&Vs[kr * AST + tcol * 4];
            float p[4];
#pragma unroll
            for (int i = 0; i < 4; i++) p[i] = Ss[(trow * 4 + i) * AST + kr];
#pragma unroll
            for (int i = 0; i < 4; i++) {
                o[i][0] = fmaf(p[i], vv.x, o[i][0]);
                o[i][1] = fmaf(p[i], vv.y, o[i][1]);
                o[i][2] = fmaf(p[i], vv.z, o[i][2]);
                o[i][3] = fmaf(p[i], vv.w, o[i][3]);
            }
        }
        __syncthreads();
    }

    // finalize: divide by l, store (merged-head layout [B*S, EMB])
#pragma unroll
    for (int i = 0; i < 4; i++) {
        int qr = trow * 4 + i;
        float inv = 1.f / l_s[qr];
        float4 ov = make_float4(o[i][0] * inv, o[i][1] * inv, o[i][2] * inv, o[i][3] * inv);
        *(float4*)(O + base + (size_t)(qt * 64 + qr) * EMB + tcol * 4) = ov;
    }
}

// ------------------------------- launch --------------------------------------
extern "C" void kernel_launch(void* const* d_in, const int* in_sizes, int n_in,
                              void* d_out, int out_size) {
    const float* x     = (const float*)d_in[0];
    // d_in[1] = mask (tril causal; applied structurally in attn_kernel)
    const float* ln1_g = (const float*)d_in[2];
    const float* ln1_b = (const float*)d_in[3];
    const float* wq    = (const float*)d_in[4];
    const float* bq    = (const float*)d_in[5];
    const float* wk    = (const float*)d_in[6];
    const float* bk    = (const float*)d_in[7];
    const float* wv    = (const float*)d_in[8];
    const float* bv    = (const float*)d_in[9];
    const float* wo    = (const float*)d_in[10];
    const float* bo    = (const float*)d_in[11];
    const float* ln2_g = (const float*)d_in[12];
    const float* ln2_b = (const float*)d_in[13];
    const float* w1    = (const float*)d_in[14];
    const float* b1    = (const float*)d_in[15];
    const float* w2    = (const float*)d_in[16];
    const float* b2    = (const float*)d_in[17];
    float* out = (float*)d_out;

    float *h, *q, *k, *v, *at, *x1, *h2, *ff;
    cudaGetSymbolAddress((void**)&h,  g_h);
    cudaGetSymbolAddress((void**)&q,  g_q);
    cudaGetSymbolAddress((void**)&k,  g_k);
    cudaGetSymbolAddress((void**)&v,  g_v);
    cudaGetSymbolAddress((void**)&at, g_at);
    cudaGetSymbolAddress((void**)&x1, g_x1);
    cudaGetSymbolAddress((void**)&h2, g_h2);
    cudaGetSymbolAddress((void**)&ff, g_ff);

    const int ATTN_SMEM = (4 * 64 * AST + 3 * 64) * sizeof(float);  // ~70 KB
    cudaFuncSetAttribute(attn_kernel, cudaFuncAttributeMaxDynamicSharedMemorySize, ATTN_SMEM);

    // LN1
    ln_kernel<<<TOK, 256>>>(x, ln1_g, ln1_b, h);
    // QKV projections
    dim3 gE(EMB / 64, TOK / 64);
    sgemm_kernel<0><<<gE, 256>>>(h, wq, bq, nullptr, q, TOK, EMB, EMB);
    sgemm_kernel<0><<<gE, 256>>>(h, wk, bk, nullptr, k, TOK, EMB, EMB);
    sgemm_kernel<0><<<gE, 256>>>(h, wv, bv, nullptr, v, TOK, EMB, EMB);
    // attention
    attn_kernel<<<dim3(SEQ / 64, 2 * NHEAD), 256, ATTN_SMEM>>>(q, k, v, at);
    // output projection + residual
    sgemm_kernel<0><<<gE, 256>>>(at, wo, bo, x, x1, TOK, EMB, EMB);
    // LN2
    ln_kernel<<<TOK, 256>>>(x1, ln2_g, ln2_b, h2);
    // FFN
    dim3 gF1(FFD / 64, TOK / 64);
    sgemm_kernel<1><<<gF1, 256>>>(h2, w1, b1, nullptr, ff, TOK, FFD, EMB);
    sgemm_kernel<0><<<gE, 256>>>(ff, w2, b2, x1, out, TOK, EMB, FFD);
}

// round 2
// speedup vs baseline: 2.0974x; 2.0974x over previous
#include <cuda_runtime.h>
#include <math.h>

#define TOK   4096          // B*S
#define SEQ   2048
#define EMB   1024
#define NHEAD 16
#define HDIM  64
#define FFD   4096

// -------- scratch (static device globals; no allocation in kernel_launch) ----
__device__ float g_h  [TOK * EMB];
__device__ float g_q  [TOK * EMB];
__device__ float g_k  [TOK * EMB];
__device__ float g_v  [TOK * EMB];
__device__ float g_at [TOK * EMB];
__device__ float g_x1 [TOK * EMB];
__device__ float g_h2 [TOK * EMB];
__device__ float g_ff [TOK * FFD];

// ------------------------------- LayerNorm -----------------------------------
__global__ void ln_kernel(const float* __restrict__ x, const float* __restrict__ g,
                          const float* __restrict__ b, float* __restrict__ out) {
    int t = blockIdx.x;
    int tid = threadIdx.x;
    const float* row = x + (size_t)t * EMB;
    float vals[4];
    float sum = 0.f, sq = 0.f;
#pragma unroll
    for (int it = 0; it < 4; it++) {
        float v = row[tid + it * 256];
        vals[it] = v; sum += v; sq += v * v;
    }
    __shared__ float s1[256], s2[256];
    s1[tid] = sum; s2[tid] = sq;
    __syncthreads();
    for (int st = 128; st > 0; st >>= 1) {
        if (tid < st) { s1[tid] += s1[tid + st]; s2[tid] += s2[tid + st]; }
        __syncthreads();
    }
    float mu   = s1[0] * (1.f / EMB);
    float var  = s2[0] * (1.f / EMB) - mu * mu;
    float rstd = rsqrtf(var + 1e-5f);
#pragma unroll
    for (int it = 0; it < 4; it++) {
        int i = tid + it * 256;
        out[(size_t)t * EMB + i] = (vals[it] - mu) * rstd * g[i] + b[i];
    }
}

// --------------------------- TF32 tensor-core GEMM ---------------------------
__device__ __forceinline__ float to_tf32(float x) {
    float r;
    asm("cvt.rna.tf32.f32 %0, %1;" : "=f"(r) : "f"(x));
    return r;
}

__device__ __forceinline__ void mma_tf32(float* d, const float* a, const float* b) {
    asm volatile(
        "mma.sync.aligned.m16n8k8.row.col.f32.tf32.tf32.f32 "
        "{%0,%1,%2,%3},{%4,%5,%6,%7},{%8,%9},{%0,%1,%2,%3};"
        : "+f"(d[0]), "+f"(d[1]), "+f"(d[2]), "+f"(d[3])
        : "r"(__float_as_uint(a[0])), "r"(__float_as_uint(a[1])),
          "r"(__float_as_uint(a[2])), "r"(__float_as_uint(a[3])),
          "r"(__float_as_uint(b[0])), "r"(__float_as_uint(b[1])));
}

#define ASTRIDE 20    // pad -> conflict-free A fragment loads
#define BSTRIDE 136   // pad -> conflict-free B fragment loads

// C[M,N] = act( A[M,K] @ B[K,N] + bias[N] + (res ? res : 0) )
// 128x128 tile, BK=16, 256 threads (8 warps, 2x4 warp grid, 64x32 per warp).
template <int ACT>
__global__ __launch_bounds__(256)
void tf32_gemm(const float* __restrict__ A, const float* __restrict__ B,
               const float* __restrict__ bias, const float* __restrict__ res,
               float* __restrict__ C, int M, int N, int K) {
    __shared__ float As[2][128][ASTRIDE];
    __shared__ float Bs[2][16][BSTRIDE];

    int tid  = threadIdx.x;
    int lane = tid & 31, warp = tid >> 5;
    int g = lane >> 2, t = lane & 3;
    int wm = (warp >> 2) * 64;     // 0 or 64
    int wn = (warp & 3) * 32;      // 0,32,64,96
    int m0 = blockIdx.y * 128, n0 = blockIdx.x * 128;

    // global load mapping: A tile 128x16 (512 float4), B tile 16x128 (512 float4)
    int a_r  = tid >> 2;           // 0..63  (second load: +64)
    int a_c  = (tid & 3) * 4;
    int b_r  = tid >> 5;           // 0..7   (second load: +8)
    int b_c  = (tid & 31) * 4;

    const float* pA0 = A + (size_t)(m0 + a_r) * K + a_c;
    const float* pA1 = pA0 + (size_t)64 * K;
    const float* pB0 = B + (size_t)b_r * N + n0 + b_c;
    const float* pB1 = pB0 + (size_t)8 * N;

    float4 ra0, ra1, rb0, rb1;

    ra0 = *(const float4*)(pA0);
    ra1 = *(const float4*)(pA1);
    rb0 = *(const float4*)(pB0);
    rb1 = *(const float4*)(pB1);

#define STORE_TILES(bufi)                                                      \
    do {                                                                       \
        float4 ca0 = make_float4(to_tf32(ra0.x), to_tf32(ra0.y),               \
                                 to_tf32(ra0.z), to_tf32(ra0.w));              \
        float4 ca1 = make_float4(to_tf32(ra1.x), to_tf32(ra1.y),               \
                                 to_tf32(ra1.z), to_tf32(ra1.w));              \
        float4 cb0 = make_float4(to_tf32(rb0.x), to_tf32(rb0.y),               \
                                 to_tf32(rb0.z), to_tf32(rb0.w));              \
        float4 cb1 = make_float4(to_tf32(rb1.x), to_tf32(rb1.y),               \
                                 to_tf32(rb1.z), to_tf32(rb1.w));              \
        *(float4*)&As[bufi][a_r][a_c]      = ca0;                              \
        *(float4*)&As[bufi][a_r + 64][a_c] = ca1;                              \
        *(float4*)&Bs[bufi][b_r][b_c]      = cb0;                              \
        *(float4*)&Bs[bufi][b_r + 8][b_c]  = cb1;                              \
    } while (0)

    STORE_TILES(0);
    __syncthreads();

    float acc[4][4][4] = {};
    int nkb = K >> 4;

    for (int kb = 0; kb < nkb; kb++) {
        int buf = kb & 1;
        if (kb + 1 < nkb) {
            const float* qA0 = pA0 + (kb + 1) * 16;
            const float* qB0 = pB0 + (size_t)(kb + 1) * 16 * N;
            ra0 = *(const float4*)(qA0);
            ra1 = *(const float4*)(qA0 + (size_t)64 * K);
            rb0 = *(const float4*)(qB0);
            rb1 = *(const float4*)(qB0 + (size_t)8 * N);
        }

#pragma unroll
        for (int kk = 0; kk < 2; kk++) {
            float a[4][4], b[4][2];
#pragma unroll
            for (int mf = 0; mf < 4; mf++) {
                int r = wm + mf * 16;
                a[mf][0] = As[buf][r + g]    [kk * 8 + t];
                a[mf][1] = As[buf][r + g + 8][kk * 8 + t];
                a[mf][2] = As[buf][r + g]    [kk * 8 + t + 4];
                a[mf][3] = As[buf][r + g + 8][kk * 8 + t + 4];
            }
#pragma unroll
            for (int nf = 0; nf < 4; nf++) {
                int c = wn + nf * 8 + g;
                b[nf][0] = Bs[buf][kk * 8 + t]    [c];
                b[nf][1] = Bs[buf][kk * 8 + t + 4][c];
            }
#pragma unroll
            for (int mf = 0; mf < 4; mf++)
#pragma unroll
                for (int nf = 0; nf < 4; nf++)
                    mma_tf32(acc[mf][nf], a[mf], b[nf]);
        }

        if (kb + 1 < nkb) {
            STORE_TILES(buf ^ 1);
            __syncthreads();
        }
    }
#undef STORE_TILES

    // ------------------------------ epilogue ---------------------------------
#pragma unroll
    for (int mf = 0; mf < 4; mf++) {
#pragma unroll
        for (int nf = 0; nf < 4; nf++) {
            int mA = m0 + wm + mf * 16 + g;
            int mB = mA + 8;
            int n_ = n0 + wn + nf * 8 + 2 * t;
            float bn0 = bias[n_], bn1 = bias[n_ + 1];

            float v00 = acc[mf][nf][0] + bn0;
            float v01 = acc[mf][nf][1] + bn1;
            float v10 = acc[mf][nf][2] + bn0;
            float v11 = acc[mf][nf][3] + bn1;
            if (res) {
                const float2 r0 = *(const float2*)(res + (size_t)mA * N + n_);
                const float2 r1 = *(const float2*)(res + (size_t)mB * N + n_);
                v00 += r0.x; v01 += r0.y; v10 += r1.x; v11 += r1.y;
            }
            if (ACT == 1) {
                v00 = 0.5f * v00 * (1.f + erff(v00 * 0.70710678118654752f));
                v01 = 0.5f * v01 * (1.f + erff(v01 * 0.70710678118654752f));
                v10 = 0.5f * v10 * (1.f + erff(v10 * 0.70710678118654752f));
                v11 = 0.5f * v11 * (1.f + erff(v11 * 0.70710678118654752f));
            }
            *(float2*)(C + (size_t)mA * N + n_) = make_float2(v00, v01);
            *(float2*)(C + (size_t)mB * N + n_) = make_float2(v10, v11);
        }
    }
}

// ---------------------------- Flash attention --------------------------------
#define AST 68
__global__ void attn_kernel(const float* __restrict__ Q, const float* __restrict__ K,
                            const float* __restrict__ V, float* __restrict__ O) {
    extern __shared__ float smem[];
    float* Qs = smem;
    float* Ks = Qs + 64 * AST;
    float* Vs = Ks + 64 * AST;
    float* Ss = Vs + 64 * AST;
    float* m_s  = Ss + 64 * AST;
    float* l_s  = m_s + 64;
    float* resc = l_s + 64;

    int qt = blockIdx.x;
    int bh = blockIdx.y;
    int bb = bh / NHEAD;
    int hh = bh % NHEAD;
    int tid  = threadIdx.x;
    int trow = tid >> 4, tcol = tid & 15;

    size_t base = (size_t)bb * SEQ * EMB + (size_t)hh * HDIM;

#pragma unroll
    for (int it = 0; it < 4; it++) {
        int r  = (tid >> 4) + it * 16;
        int d4 = tid & 15;
        *(float4*)&Qs[r * AST + d4 * 4] =
            *(const float4*)(Q + base + (size_t)(qt * 64 + r) * EMB + d4 * 4);
    }
    if (tid < 64) { m_s[tid] = -1e30f; l_s[tid] = 0.f; }
    float o[4][4] = {};
    __syncthreads();

    const float scale = 0.125f;

    for (int kt = 0; kt <= qt; kt++) {
#pragma unroll
        for (int it = 0; it < 4; it++) {
            int r  = (tid >> 4) + it * 16;
            int d4 = tid & 15;
            size_t goff = base + (size_t)(kt * 64 + r) * EMB + d4 * 4;
            *(float4*)&Ks[r * AST + d4 * 4] = *(const float4*)(K + goff);
            *(float4*)&Vs[r * AST + d4 * 4] = *(const float4*)(V + goff);
        }
        __syncthreads();

        float s[4][4] = {};
#pragma unroll
        for (int d4 = 0; d4 < 16; d4++) {
            float4 qv[4], kv[4];
#pragma unroll
            for (int i = 0; i < 4; i++)
                qv[i] = *(const float4*)&Qs[(trow * 4 + i) * AST + d4 * 4];
#pragma unroll
            for (int j = 0; j < 4; j++)
                kv[j] = *(const float4*)&Ks[(tcol * 4 + j) * AST + d4 * 4];
#pragma unroll
            for (int i = 0; i < 4; i++)
#pragma unroll
                for (int j = 0; j < 4; j++) {
                    s[i][j] = fmaf(qv[i].x, kv[j].x, s[i][j]);
                    s[i][j] = fmaf(qv[i].y, kv[j].y, s[i][j]);
                    s[i][j] = fmaf(qv[i].z, kv[j].z, s[i][j]);
                    s[i][j] = fmaf(qv[i].w, kv[j].w, s[i][j]);
                }
        }
        bool diag = (kt == qt);
#pragma unroll
        for (int i = 0; i < 4; i++) {
            int qr = trow * 4 + i;
#pragma unroll
            for (int j = 0; j < 4; j++) {
                int kr = tcol * 4 + j;
                float v = s[i][j] * scale;
                if (diag && kr > qr) v = -1e30f;
                Ss[qr * AST + kr] = v;
            }
        }
        __syncthreads();

        if (tid < 64) {
            int r = tid;
            float mold = m_s[r];
            float rowmax = -1e30f;
#pragma unroll 8
            for (int c = 0; c < 64; c++) rowmax = fmaxf(rowmax, Ss[r * AST + c]);
            float mnew = fmaxf(mold, rowmax);
            float rs = __expf(mold - mnew);
            float sum = 0.f;
#pragma unroll 8
            for (int c = 0; c < 64; c++) {
                float p = __expf(Ss[r * AST + c] - mnew);
                Ss[r * AST + c] = p;
                sum += p;
            }
            l_s[r]  = l_s[r] * rs + sum;
            m_s[r]  = mnew;
            resc[r] = rs;
        }
        __syncthreads();

#pragma unroll
        for (int i = 0; i < 4; i++) {
            float rs = resc[trow * 4 + i];
#pragma unroll
            for (int j = 0; j < 4; j++) o[i][j] *= rs;
        }
#pragma unroll 4
        for (int kr = 0; kr < 64; kr++) {
            float4 vv = *(const float4*)&Vs[kr * AST + tcol * 4];
            float p[4];
#pragma unroll
            for (int i = 0; i < 4; i++) p[i] = Ss[(trow * 4 + i) * AST + kr];
#pragma unroll
            for (int i = 0; i < 4; i++) {
                o[i][0] = fmaf(p[i], vv.x, o[i][0]);
                o[i][1] = fmaf(p[i], vv.y, o[i][1]);
                o[i][2] = fmaf(p[i], vv.z, o[i][2]);
                o[i][3] = fmaf(p[i], vv.w, o[i][3]);
            }
        }
        __syncthreads();
    }

#pragma unroll
    for (int i = 0; i < 4; i++) {
        int qr = trow * 4 + i;
        float inv = 1.f / l_s[qr];
        float4 ov = make_float4(o[i][0] * inv, o[i][1] * inv, o[i][2] * inv, o[i][3] * inv);
        *(float4*)(O + base + (size_t)(qt * 64 + qr) * EMB + tcol * 4) = ov;
    }
}

// ------------------------------- launch --------------------------------------
extern "C" void kernel_launch(void* const* d_in, const int* in_sizes, int n_in,
                              void* d_out, int out_size) {
    const float* x     = (const float*)d_in[0];
    const float* ln1_g = (const float*)d_in[2];
    const float* ln1_b = (const float*)d_in[3];
    const float* wq    = (const float*)d_in[4];
    const float* bq    = (const float*)d_in[5];
    const float* wk    = (const float*)d_in[6];
    const float* bk    = (const float*)d_in[7];
    const float* wv    = (const float*)d_in[8];
    const float* bv    = (const float*)d_in[9];
    const float* wo    = (const float*)d_in[10];
    const float* bo    = (const float*)d_in[11];
    const float* ln2_g = (const float*)d_in[12];
    const float* ln2_b = (const float*)d_in[13];
    const float* w1    = (const float*)d_in[14];
    const float* b1    = (const float*)d_in[15];
    const float* w2    = (const float*)d_in[16];
    const float* b2    = (const float*)d_in[17];
    float* out = (float*)d_out;

    float *h, *q, *k, *v, *at, *x1, *h2, *ff;
    cudaGetSymbolAddress((void**)&h,  g_h);
    cudaGetSymbolAddress((void**)&q,  g_q);
    cudaGetSymbolAddress((void**)&k,  g_k);
    cudaGetSymbolAddress((void**)&v,  g_v);
    cudaGetSymbolAddress((void**)&at, g_at);
    cudaGetSymbolAddress((void**)&x1, g_x1);
    cudaGetSymbolAddress((void**)&h2, g_h2);
    cudaGetSymbolAddress((void**)&ff, g_ff);

    const int ATTN_SMEM = (4 * 64 * AST + 3 * 64) * sizeof(float);
    cudaFuncSetAttribute(attn_kernel, cudaFuncAttributeMaxDynamicSharedMemorySize, ATTN_SMEM);

    ln_kernel<<<TOK, 256>>>(x, ln1_g, ln1_b, h);

    dim3 gE(EMB / 128, TOK / 128);       // (8, 32)
    tf32_gemm<0><<<gE, 256>>>(h, wq, bq, nullptr, q, TOK, EMB, EMB);
    tf32_gemm<0><<<gE, 256>>>(h, wk, bk, nullptr, k, TOK, EMB, EMB);
    tf32_gemm<0><<<gE, 256>>>(h, wv, bv, nullptr, v, TOK, EMB, EMB);

    attn_kernel<<<dim3(SEQ / 64, 2 * NHEAD), 256, ATTN_SMEM>>>(q, k, v, at);

    tf32_gemm<0><<<gE, 256>>>(at, wo, bo, x, x1, TOK, EMB, EMB);

    ln_kernel<<<TOK, 256>>>(x1, ln2_g, ln2_b, h2);

    dim3 gF1(FFD / 128, TOK / 128);      // (32, 32)
    tf32_gemm<1><<<gF1, 256>>>(h2, w1, b1, nullptr, ff, TOK, FFD, EMB);
    tf32_gemm<0><<<gE, 256>>>(ff, w2, b2, x1, out, TOK, EMB, FFD);
}

// round 3
// speedup vs baseline: 3.7459x; 1.7859x over previous
#include <cuda_runtime.h>
#include <math.h>

#define TOK   4096          // B*S
#define SEQ   2048
#define EMB   1024
#define NHEAD 16
#define HDIM  64
#define FFD   4096

// -------- scratch ----
__device__ float g_h  [TOK * EMB];
__device__ float g_q  [TOK * EMB];
__device__ float g_k  [TOK * EMB];
__device__ float g_v  [TOK * EMB];
__device__ float g_at [TOK * EMB];
__device__ float g_x1 [TOK * EMB];
__device__ float g_h2 [TOK * EMB];
__device__ float g_ff [TOK * FFD];

// ------------------------------- LayerNorm -----------------------------------
__global__ void ln_kernel(const float* __restrict__ x, const float* __restrict__ g,
                          const float* __restrict__ b, float* __restrict__ out) {
    int t = blockIdx.x;
    int tid = threadIdx.x;
    const float* row = x + (size_t)t * EMB;
    float vals[4];
    float sum = 0.f, sq = 0.f;
#pragma unroll
    for (int it = 0; it < 4; it++) {
        float v = row[tid + it * 256];
        vals[it] = v; sum += v; sq += v * v;
    }
    __shared__ float s1[256], s2[256];
    s1[tid] = sum; s2[tid] = sq;
    __syncthreads();
    for (int st = 128; st > 0; st >>= 1) {
        if (tid < st) { s1[tid] += s1[tid + st]; s2[tid] += s2[tid + st]; }
        __syncthreads();
    }
    float mu   = s1[0] * (1.f / EMB);
    float var  = s2[0] * (1.f / EMB) - mu * mu;
    float rstd = rsqrtf(var + 1e-5f);
#pragma unroll
    for (int it = 0; it < 4; it++) {
        int i = tid + it * 256;
        out[(size_t)t * EMB + i] = (vals[it] - mu) * rstd * g[i] + b[i];
    }
}

// --------------------------- TF32 helpers -------------------------------------
__device__ __forceinline__ float to_tf32(float x) {
    float r;
    asm("cvt.rna.tf32.f32 %0, %1;" : "=f"(r) : "f"(x));
    return r;
}
__device__ __forceinline__ float4 cvt4(float4 v) {
    return make_float4(to_tf32(v.x), to_tf32(v.y), to_tf32(v.z), to_tf32(v.w));
}
__device__ __forceinline__ void mma_tf32(float* d, const float* a, const float* b) {
    asm volatile(
        "mma.sync.aligned.m16n8k8.row.col.f32.tf32.tf32.f32 "
        "{%0,%1,%2,%3},{%4,%5,%6,%7},{%8,%9},{%0,%1,%2,%3};"
        : "+f"(d[0]), "+f"(d[1]), "+f"(d[2]), "+f"(d[3])
        : "r"(__float_as_uint(a[0])), "r"(__float_as_uint(a[1])),
          "r"(__float_as_uint(a[2])), "r"(__float_as_uint(a[3])),
          "r"(__float_as_uint(b[0])), "r"(__float_as_uint(b[1])));
}

// --------------------------- TF32 tensor-core GEMM ---------------------------
#define ASTRIDE 20
#define BSTRIDE 136

template <int ACT>
__global__ __launch_bounds__(256)
void tf32_gemm(const float* __restrict__ A, const float* __restrict__ B,
               const float* __restrict__ bias, const float* __restrict__ res,
               float* __restrict__ C, int M, int N, int K) {
    __shared__ float As[2][128][ASTRIDE];
    __shared__ float Bs[2][16][BSTRIDE];

    int tid  = threadIdx.x;
    int lane = tid & 31, warp = tid >> 5;
    int g = lane >> 2, t = lane & 3;
    int wm = (warp >> 2) * 64;
    int wn = (warp & 3) * 32;
    int m0 = blockIdx.y * 128, n0 = blockIdx.x * 128;

    int a_r  = tid >> 2;
    int a_c  = (tid & 3) * 4;
    int b_r  = tid >> 5;
    int b_c  = (tid & 31) * 4;

    const float* pA0 = A + (size_t)(m0 + a_r) * K + a_c;
    const float* pA1 = pA0 + (size_t)64 * K;
    const float* pB0 = B + (size_t)b_r * N + n0 + b_c;
    const float* pB1 = pB0 + (size_t)8 * N;

    float4 ra0, ra1, rb0, rb1;
    ra0 = *(const float4*)(pA0);
    ra1 = *(const float4*)(pA1);
    rb0 = *(const float4*)(pB0);
    rb1 = *(const float4*)(pB1);

#define STORE_TILES(bufi)                                                      \
    do {                                                                       \
        *(float4*)&As[bufi][a_r][a_c]      = cvt4(ra0);                        \
        *(float4*)&As[bufi][a_r + 64][a_c] = cvt4(ra1);                        \
        *(float4*)&Bs[bufi][b_r][b_c]      = cvt4(rb0);                        \
        *(float4*)&Bs[bufi][b_r + 8][b_c]  = cvt4(rb1);                        \
    } while (0)

    STORE_TILES(0);
    __syncthreads();

    float acc[4][4][4] = {};
    int nkb = K >> 4;

    for (int kb = 0; kb < nkb; kb++) {
        int buf = kb & 1;
        if (kb + 1 < nkb) {
            const float* qA0 = pA0 + (kb + 1) * 16;
            const float* qB0 = pB0 + (size_t)(kb + 1) * 16 * N;
            ra0 = *(const float4*)(qA0);
            ra1 = *(const float4*)(qA0 + (size_t)64 * K);
            rb0 = *(const float4*)(qB0);
            rb1 = *(const float4*)(qB0 + (size_t)8 * N);
        }

#pragma unroll
        for (int kk = 0; kk < 2; kk++) {
            float a[4][4], b[4][2];
#pragma unroll
            for (int mf = 0; mf < 4; mf++) {
                int r = wm + mf * 16;
                a[mf][0] = As[buf][r + g]    [kk * 8 + t];
                a[mf][1] = As[buf][r + g + 8][kk * 8 + t];
                a[mf][2] = As[buf][r + g]    [kk * 8 + t + 4];
                a[mf][3] = As[buf][r + g + 8][kk * 8 + t + 4];
            }
#pragma unroll
            for (int nf = 0; nf < 4; nf++) {
                int c = wn + nf * 8 + g;
                b[nf][0] = Bs[buf][kk * 8 + t]    [c];
                b[nf][1] = Bs[buf][kk * 8 + t + 4][c];
            }
#pragma unroll
            for (int mf = 0; mf < 4; mf++)
#pragma unroll
                for (int nf = 0; nf < 4; nf++)
                    mma_tf32(acc[mf][nf], a[mf], b[nf]);
        }

        if (kb + 1 < nkb) {
            STORE_TILES(buf ^ 1);
            __syncthreads();
        }
    }
#undef STORE_TILES

#pragma unroll
    for (int mf = 0; mf < 4; mf++) {
#pragma unroll
        for (int nf = 0; nf < 4; nf++) {
            int mA = m0 + wm + mf * 16 + g;
            int mB = mA + 8;
            int n_ = n0 + wn + nf * 8 + 2 * t;
            float bn0 = bias[n_], bn1 = bias[n_ + 1];

            float v00 = acc[mf][nf][0] + bn0;
            float v01 = acc[mf][nf][1] + bn1;
            float v10 = acc[mf][nf][2] + bn0;
            float v11 = acc[mf][nf][3] + bn1;
            if (res) {
                const float2 r0 = *(const float2*)(res + (size_t)mA * N + n_);
                const float2 r1 = *(const float2*)(res + (size_t)mB * N + n_);
                v00 += r0.x; v01 += r0.y; v10 += r1.x; v11 += r1.y;
            }
            if (ACT == 1) {
                v00 = 0.5f * v00 * (1.f + erff(v00 * 0.70710678118654752f));
                v01 = 0.5f * v01 * (1.f + erff(v01 * 0.70710678118654752f));
                v10 = 0.5f * v10 * (1.f + erff(v10 * 0.70710678118654752f));
                v11 = 0.5f * v11 * (1.f + erff(v11 * 0.70710678118654752f));
            }
            *(float2*)(C + (size_t)mA * N + n_) = make_float2(v00, v01);
            *(float2*)(C + (size_t)mB * N + n_) = make_float2(v10, v11);
        }
    }
}

// -------------------- Tensor-core flash attention (tf32) ----------------------
// Block: 128 threads (4 warps). 64 Q rows per CTA; each warp owns 16 rows.
// Ks stride 68 (conflict-free B-frag: 4g+t), Vs stride 72 (8t+g), Ss stride 68.
#define KST 68
#define VST 72
#define SST 68

__global__ __launch_bounds__(128)
void attn_tc(const float* __restrict__ Q, const float* __restrict__ K,
             const float* __restrict__ V, float* __restrict__ O) {
    extern __shared__ float sm[];
    float* Ks = sm;                    // 64 x KST
    float* Vs = Ks + 64 * KST;         // 64 x VST
    float* Ss = Vs + 64 * VST;         // 64 x SST (Q staging, then P buffer)

    int qt = (int)gridDim.x - 1 - (int)blockIdx.x;   // long CTAs first
    int bh = blockIdx.y;
    int bb = bh >> 4, hh = bh & 15;
    int tid  = threadIdx.x;
    int warp = tid >> 5, lane = tid & 31;
    int g = lane >> 2, t = lane & 3;
    int r0 = warp * 16;

    size_t base = (size_t)bb * SEQ * EMB + (size_t)hh * HDIM;

    // ---- stage Q (scaled + tf32) via Ss, pull A-fragments into registers ----
#pragma unroll
    for (int it = 0; it < 8; it++) {
        int r = (tid >> 4) + it * 8;
        int c = (tid & 15) * 4;
        float4 v = *(const float4*)(Q + base + (size_t)(qt * 64 + r) * EMB + c);
        float4 w = make_float4(to_tf32(v.x * 0.125f), to_tf32(v.y * 0.125f),
                               to_tf32(v.z * 0.125f), to_tf32(v.w * 0.125f));
        *(float4*)&Ss[r * SST + c] = w;
    }
    __syncthreads();

    float qf[8][4];
#pragma unroll
    for (int kc = 0; kc < 8; kc++) {
        qf[kc][0] = Ss[(r0 + g)     * SST + kc * 8 + t];
        qf[kc][1] = Ss[(r0 + g + 8) * SST + kc * 8 + t];
        qf[kc][2] = Ss[(r0 + g)     * SST + kc * 8 + t + 4];
        qf[kc][3] = Ss[(r0 + g + 8) * SST + kc * 8 + t + 4];
    }

    float o[8][4] = {};
    float m0 = -1e30f, m1 = -1e30f, l0 = 0.f, l1 = 0.f;

    for (int kt = 0; kt <= qt; kt++) {
        // ---- load K,V tile (tf32) ----
#pragma unroll
        for (int it = 0; it < 8; it++) {
            int r = (tid >> 4) + it * 8;
            int c = (tid & 15) * 4;
            size_t go = base + (size_t)(kt * 64 + r) * EMB + c;
            float4 kv = *(const float4*)(K + go);
            float4 vv = *(const float4*)(V + go);
            *(float4*)&Ks[r * KST + c] = cvt4(kv);
            *(float4*)&Vs[r * VST + c] = cvt4(vv);
        }
        __syncthreads();

        // ---- S = Q K^T ----
        float s[8][4];
#pragma unroll
        for (int nf = 0; nf < 8; nf++) {
            s[nf][0] = s[nf][1] = s[nf][2] = s[nf][3] = 0.f;
            const float* kr = &Ks[(nf * 8 + g) * KST];
#pragma unroll
            for (int kc = 0; kc < 8; kc++) {
                float b[2] = { kr[kc * 8 + t], kr[kc * 8 + t + 4] };
                mma_tf32(s[nf], qf[kc], b);
            }
        }

        // ---- causal mask on diagonal tile ----
        if (kt == qt) {
            int rowA = r0 + g, rowB = r0 + g + 8;
#pragma unroll
            for (int nf = 0; nf < 8; nf++) {
                int c0 = nf * 8 + 2 * t, c1 = c0 + 1;
                if (c0 > rowA) s[nf][0] = -1e30f;
                if (c1 > rowA) s[nf][1] = -1e30f;
                if (c0 > rowB) s[nf][2] = -1e30f;
                if (c1 > rowB) s[nf][3] = -1e30f;
            }
        }

        // ---- online softmax (row stats: rows r0+g and r0+g+8) ----
        float mx0 = -1e30f, mx1 = -1e30f;
#pragma unroll
        for (int nf = 0; nf < 8; nf++) {
            mx0 = fmaxf(mx0, fmaxf(s[nf][0], s[nf][1]));
            mx1 = fmaxf(mx1, fmaxf(s[nf][2], s[nf][3]));
        }
        mx0 = fmaxf(mx0, __shfl_xor_sync(0xffffffffu, mx0, 1));
        mx0 = fmaxf(mx0, __shfl_xor_sync(0xffffffffu, mx0, 2));
        mx1 = fmaxf(mx1, __shfl_xor_sync(0xffffffffu, mx1, 1));
        mx1 = fmaxf(mx1, __shfl_xor_sync(0xffffffffu, mx1, 2));

        float m0n = fmaxf(m0, mx0), m1n = fmaxf(m1, mx1);
        float rs0 = __expf(m0 - m0n), rs1 = __expf(m1 - m1n);
        m0 = m0n; m1 = m1n;

        float sum0 = 0.f, sum1 = 0.f;
#pragma unroll
        for (int nf = 0; nf < 8; nf++) {
            s[nf][0] = __expf(s[nf][0] - m0);
            s[nf][1] = __expf(s[nf][1] - m0);
            s[nf][2] = __expf(s[nf][2] - m1);
            s[nf][3] = __expf(s[nf][3] - m1);
            sum0 += s[nf][0] + s[nf][1];
            sum1 += s[nf][2] + s[nf][3];
        }
        sum0 += __shfl_xor_sync(0xffffffffu, sum0, 1);
        sum0 += __shfl_xor_sync(0xffffffffu, sum0, 2);
        sum1 += __shfl_xor_sync(0xffffffffu, sum1, 1);
        sum1 += __shfl_xor_sync(0xffffffffu, sum1, 2);
        l0 = l0 * rs0 + sum0;
        l1 = l1 * rs1 + sum1;

        // ---- store P (tf32) to own strip ----
        __syncwarp();
#pragma unroll
        for (int nf = 0; nf < 8; nf++) {
            int c = nf * 8 + 2 * t;
            *(float2*)&Ss[(r0 + g)     * SST + c] =
                make_float2(to_tf32(s[nf][0]), to_tf32(s[nf][1]));
            *(float2*)&Ss[(r0 + g + 8) * SST + c] =
                make_float2(to_tf32(s[nf][2]), to_tf32(s[nf][3]));
        }
        __syncwarp();

        // ---- rescale O, then O += P @ V ----
#pragma unroll
        for (int nf = 0; nf < 8; nf++) {
            o[nf][0] *= rs0; o[nf][1] *= rs0;
            o[nf][2] *= rs1; o[nf][3] *= rs1;
        }
#pragma unroll
        for (int kc = 0; kc < 8; kc++) {
            float pf[4];
            pf[0] = Ss[(r0 + g)     * SST + kc * 8 + t];
            pf[1] = Ss[(r0 + g + 8) * SST + kc * 8 + t];
            pf[2] = Ss[(r0 + g)     * SST + kc * 8 + t + 4];
            pf[3] = Ss[(r0 + g + 8) * SST + kc * 8 + t + 4];
            const float* v0 = &Vs[(kc * 8 + t)     * VST];
            const float* v1 = &Vs[(kc * 8 + t + 4) * VST];
#pragma unroll
            for (int nf = 0; nf < 8; nf++) {
                float b[2] = { v0[nf * 8 + g], v1[nf * 8 + g] };
                mma_tf32(o[nf], pf, b);
            }
        }
        __syncthreads();   // before K/V overwrite next tile
    }

    // ---- epilogue: divide by l, store ----
    float il0 = 1.f / l0, il1 = 1.f / l1;
    int rowA = qt * 64 + r0 + g;
    int rowB = rowA + 8;
#pragma unroll
    for (int nf = 0; nf < 8; nf++) {
        int c = nf * 8 + 2 * t;
        *(float2*)(O + base + (size_t)rowA * EMB + c) =
            make_float2(o[nf][0] * il0, o[nf][1] * il0);
        *(float2*)(O + base + (size_t)rowB * EMB + c) =
            make_float2(o[nf][2] * il1, o[nf][3] * il1);
    }
}

// ------------------------------- launch --------------------------------------
extern "C" void kernel_launch(void* const* d_in, const int* in_sizes, int n_in,
                              void* d_out, int out_size) {
    const float* x     = (const float*)d_in[0];
    const float* ln1_g = (const float*)d_in[2];
    const float* ln1_b = (const float*)d_in[3];
    const float* wq    = (const float*)d_in[4];
    const float* bq    = (const float*)d_in[5];
    const float* wk    = (const float*)d_in[6];
    const float* bk    = (const float*)d_in[7];
    const float* wv    = (const float*)d_in[8];
    const float* bv    = (const float*)d_in[9];
    const float* wo    = (const float*)d_in[10];
    const float* bo    = (const float*)d_in[11];
    const float* ln2_g = (const float*)d_in[12];
    const float* ln2_b = (const float*)d_in[13];
    const float* w1    = (const float*)d_in[14];
    const float* b1    = (const float*)d_in[15];
    const float* w2    = (const float*)d_in[16];
    const float* b2    = (const float*)d_in[17];
    float* out = (float*)d_out;

    float *h, *q, *k, *v, *at, *x1, *h2, *ff;
    cudaGetSymbolAddress((void**)&h,  g_h);
    cudaGetSymbolAddress((void**)&q,  g_q);
    cudaGetSymbolAddress((void**)&k,  g_k);
    cudaGetSymbolAddress((void**)&v,  g_v);
    cudaGetSymbolAddress((void**)&at, g_at);
    cudaGetSymbolAddress((void**)&x1, g_x1);
    cudaGetSymbolAddress((void**)&h2, g_h2);
    cudaGetSymbolAddress((void**)&ff, g_ff);

    const int ATTN_SMEM = (64 * KST + 64 * VST + 64 * SST) * sizeof(float); // ~52KB
    cudaFuncSetAttribute(attn_tc, cudaFuncAttributeMaxDynamicSharedMemorySize, ATTN_SMEM);

    ln_kernel<<<TOK, 256>>>(x, ln1_g, ln1_b, h);

    dim3 gE(EMB / 128, TOK / 128);
    tf32_gemm<0><<<gE, 256>>>(h, wq, bq, nullptr, q, TOK, EMB, EMB);
    tf32_gemm<0><<<gE, 256>>>(h, wk, bk, nullptr, k, TOK, EMB, EMB);
    tf32_gemm<0><<<gE, 256>>>(h, wv, bv, nullptr, v, TOK, EMB, EMB);

    attn_tc<<<dim3(SEQ / 64, 2 * NHEAD), 128, ATTN_SMEM>>>(q, k, v, at);

    tf32_gemm<0><<<gE, 256>>>(at, wo, bo, x, x1, TOK, EMB, EMB);

    ln_kernel<<<TOK, 256>>>(x1, ln2_g, ln2_b, h2);

    dim3 gF1(FFD / 128, TOK / 128);
    tf32_gemm<1><<<gF1, 256>>>(h2, w1, b1, nullptr, ff, TOK, FFD, EMB);
    tf32_gemm<0><<<gE, 256>>>(ff, w2, b2, x1, out, TOK, EMB, FFD);
}